// round 3
// baseline (speedup 1.0000x reference)
#include <cuda_runtime.h>
#include <cstdint>
#include <cstddef>

// Problem constants
#define H_DIM   2048
#define S_LEN   2048
#define B_SZ    2
#define NHEADS  16
#define NKVH    8
#define HD      128
#define FF_DIM  5632
#define MROWS   (B_SZ * S_LEN)          // 4096
#define QKV_LD  4096                    // q(2048) | k(1024) | v(1024)
#define ATT_SCALE 0.08838834764831845f  // 1/sqrt(128)

// ---------------------------------------------------------------------------
// Scratch (allocation is forbidden; __device__ globals are the sanctioned path)
// ---------------------------------------------------------------------------
__device__ float g_xn  [(size_t)MROWS * H_DIM];   // rmsnorm output (reused twice)
__device__ float g_qkv [(size_t)MROWS * QKV_LD];
__device__ float g_attn[(size_t)MROWS * H_DIM];
__device__ float g_h   [(size_t)MROWS * H_DIM];   // residual-1 output
__device__ float g_gate[(size_t)MROWS * FF_DIM];
__device__ float g_up  [(size_t)MROWS * FF_DIM];
__device__ float g_ff  [(size_t)MROWS * FF_DIM];

// ---------------------------------------------------------------------------
// RMSNorm: one block per row (H=2048), 256 threads, float4
// ---------------------------------------------------------------------------
__global__ __launch_bounds__(256) void rmsnorm_k(
    const float* __restrict__ x, const float* __restrict__ w, float* __restrict__ y)
{
    const int row = blockIdx.x;
    const float4* xr = (const float4*)(x + (size_t)row * H_DIM);
    float4*       yr = (float4*)(y + (size_t)row * H_DIM);
    const float4* w4 = (const float4*)w;
    const int tid = threadIdx.x;

    float4 v0 = xr[tid];
    float4 v1 = xr[tid + 256];
    float s = v0.x*v0.x + v0.y*v0.y + v0.z*v0.z + v0.w*v0.w
            + v1.x*v1.x + v1.y*v1.y + v1.z*v1.z + v1.w*v1.w;

    #pragma unroll
    for (int off = 16; off; off >>= 1) s += __shfl_xor_sync(0xffffffffu, s, off);

    __shared__ float red[8];
    if ((tid & 31) == 0) red[tid >> 5] = s;
    __syncthreads();
    float tot = red[0] + red[1] + red[2] + red[3] + red[4] + red[5] + red[6] + red[7];
    const float inv = rsqrtf(tot * (1.0f / H_DIM) + 1e-6f);

    float4 w0 = w4[tid], w1 = w4[tid + 256];
    float4 o0, o1;
    o0.x = v0.x * inv * w0.x; o0.y = v0.y * inv * w0.y;
    o0.z = v0.z * inv * w0.z; o0.w = v0.w * inv * w0.w;
    o1.x = v1.x * inv * w1.x; o1.y = v1.y * inv * w1.y;
    o1.z = v1.z * inv * w1.z; o1.w = v1.w * inv * w1.w;
    yr[tid] = o0;
    yr[tid + 256] = o1;
}

// ---------------------------------------------------------------------------
// NT GEMM: C[m,n] = sum_k A[m,k] * B[n,k]  (+ optional residual, res ld == ldc)
// BM=BN=128, BK=16, 256 threads, 8x8 per thread.
// Grid: (N/128, M/128). All shapes here are multiples of 128 / K mult of 16.
// ---------------------------------------------------------------------------
__global__ __launch_bounds__(256) void gemm_nt(
    const float* __restrict__ A, int lda,
    const float* __restrict__ B, int ldb,
    const float* __restrict__ Res,
    float* __restrict__ C, int ldc, int K)
{
    __shared__ __align__(16) float As[16][132];
    __shared__ __align__(16) float Bs[16][132];

    const int tid = threadIdx.x;
    const int tx = tid & 15, ty = tid >> 4;
    const int m0 = blockIdx.y * 128;
    const int n0 = blockIdx.x * 128;

    const float* Ag = A + (size_t)m0 * lda;
    const float* Bg = B + (size_t)n0 * ldb;

    float acc[8][8];
    #pragma unroll
    for (int i = 0; i < 8; i++)
        #pragma unroll
        for (int j = 0; j < 8; j++) acc[i][j] = 0.0f;

    const int r0 = tid >> 2;         // 0..63
    const int c4 = (tid & 3) << 2;   // 0,4,8,12

    for (int k0 = 0; k0 < K; k0 += 16) {
        float4 a0 = *(const float4*)(Ag + (size_t)r0        * lda + k0 + c4);
        float4 a1 = *(const float4*)(Ag + (size_t)(r0 + 64) * lda + k0 + c4);
        float4 b0 = *(const float4*)(Bg + (size_t)r0        * ldb + k0 + c4);
        float4 b1 = *(const float4*)(Bg + (size_t)(r0 + 64) * ldb + k0 + c4);

        As[c4+0][r0] = a0.x; As[c4+1][r0] = a0.y; As[c4+2][r0] = a0.z; As[c4+3][r0] = a0.w;
        As[c4+0][r0+64] = a1.x; As[c4+1][r0+64] = a1.y; As[c4+2][r0+64] = a1.z; As[c4+3][r0+64] = a1.w;
        Bs[c4+0][r0] = b0.x; Bs[c4+1][r0] = b0.y; Bs[c4+2][r0] = b0.z; Bs[c4+3][r0] = b0.w;
        Bs[c4+0][r0+64] = b1.x; Bs[c4+1][r0+64] = b1.y; Bs[c4+2][r0+64] = b1.z; Bs[c4+3][r0+64] = b1.w;
        __syncthreads();

        #pragma unroll
        for (int kk = 0; kk < 16; kk++) {
            float a[8], b[8];
            *(float4*)(a)     = *(const float4*)&As[kk][ty * 8];
            *(float4*)(a + 4) = *(const float4*)&As[kk][ty * 8 + 4];
            *(float4*)(b)     = *(const float4*)&Bs[kk][tx * 8];
            *(float4*)(b + 4) = *(const float4*)&Bs[kk][tx * 8 + 4];
            #pragma unroll
            for (int i = 0; i < 8; i++)
                #pragma unroll
                for (int j = 0; j < 8; j++)
                    acc[i][j] += a[i] * b[j];
        }
        __syncthreads();
    }

    #pragma unroll
    for (int i = 0; i < 8; i++) {
        const size_t m = (size_t)(m0 + ty * 8 + i);
        float* cp = C + m * ldc + n0 + tx * 8;
        float4 v0 = make_float4(acc[i][0], acc[i][1], acc[i][2], acc[i][3]);
        float4 v1 = make_float4(acc[i][4], acc[i][5], acc[i][6], acc[i][7]);
        if (Res) {
            const float* rp = Res + m * ldc + n0 + tx * 8;
            float4 e0 = *(const float4*)rp;
            float4 e1 = *(const float4*)(rp + 4);
            v0.x += e0.x; v0.y += e0.y; v0.z += e0.z; v0.w += e0.w;
            v1.x += e1.x; v1.y += e1.y; v1.z += e1.z; v1.w += e1.w;
        }
        *(float4*)cp = v0;
        *(float4*)(cp + 4) = v1;
    }
}

// ---------------------------------------------------------------------------
// Causal flash attention, fp32, GQA (kv head = h >> 1).
// Grid (32, 16, 2): q-tile 64, k-tile 64. Block 256 (16x16 logical).
// Each thread: 4 q-rows (ty*4+i) x [4 score cols (tx*4+j) | 8 out cols (tx*8+j)].
// Smem: Qs[64][128] + Ks[64][132] + Vs[64][128] + Ps[64][64] = 113 KB dynamic.
// ---------------------------------------------------------------------------
#define FLASH_SMEM ((64*128 + 64*132 + 64*128 + 64*64) * 4)

__global__ __launch_bounds__(256) void flash_k(
    const float* __restrict__ qkv, float* __restrict__ out)
{
    extern __shared__ float sm[];
    float* Qs = sm;                 // [64][128]
    float* Ks = Qs + 64 * 128;      // [64][132] (padded vs bank conflicts)
    float* Vs = Ks + 64 * 132;      // [64][128]
    float* Ps = Vs + 64 * 128;      // [64][64]

    const int qt = gridDim.x - 1 - blockIdx.x;   // high q-tiles first (causal balance)
    const int h  = blockIdx.y;
    const int b  = blockIdx.z;
    const int kvh = h >> 1;                      // GROUPS = 2
    const int q0 = qt * 64;
    const int tid = threadIdx.x;
    const int tx = tid & 15, ty = tid >> 4;

    const float* qbase = qkv + ((size_t)(b * S_LEN + q0)) * QKV_LD + h * HD;
    const float* kbase = qkv + ((size_t)(b * S_LEN)) * QKV_LD + 2048 + kvh * HD;
    const float* vbase = kbase + 1024;

    // Load Q tile (pre-scaled by 1/sqrt(HD))
    #pragma unroll
    for (int t = 0; t < 8; t++) {
        int idx = tid + t * 256;
        int r = idx >> 5;
        int d4 = (idx & 31) << 2;
        float4 v = *(const float4*)(qbase + (size_t)r * QKV_LD + d4);
        v.x *= ATT_SCALE; v.y *= ATT_SCALE; v.z *= ATT_SCALE; v.w *= ATT_SCALE;
        *(float4*)&Qs[r * 128 + d4] = v;
    }

    float m[4], l[4], o[4][8];
    #pragma unroll
    for (int i = 0; i < 4; i++) {
        m[i] = -1e30f; l[i] = 0.0f;
        #pragma unroll
        for (int j = 0; j < 8; j++) o[i][j] = 0.0f;
    }

    for (int kt = 0; kt <= qt; kt++) {
        const int k0 = kt * 64;
        __syncthreads();  // protect Ks/Vs/Ps reuse
        #pragma unroll
        for (int t = 0; t < 8; t++) {
            int idx = tid + t * 256;
            int r = idx >> 5;
            int d4 = (idx & 31) << 2;
            *(float4*)&Ks[r * 132 + d4] = *(const float4*)(kbase + (size_t)(k0 + r) * QKV_LD + d4);
            *(float4*)&Vs[r * 128 + d4] = *(const float4*)(vbase + (size_t)(k0 + r) * QKV_LD + d4);
        }
        __syncthreads();

        // --- scores: s[i][j] = q_row(ty*4+i) . k_row(tx*4+j) ---
        float s4[4][4];
        #pragma unroll
        for (int i = 0; i < 4; i++)
            #pragma unroll
            for (int j = 0; j < 4; j++) s4[i][j] = 0.0f;

        const float* qp = &Qs[(ty * 4) * 128];
        const float* kp = &Ks[(tx * 4) * 132];
        #pragma unroll 8
        for (int d = 0; d < 128; d += 4) {
            float4 qv[4], kv[4];
            #pragma unroll
            for (int i = 0; i < 4; i++) qv[i] = *(const float4*)(qp + i * 128 + d);
            #pragma unroll
            for (int j = 0; j < 4; j++) kv[j] = *(const float4*)(kp + j * 132 + d);
            #pragma unroll
            for (int i = 0; i < 4; i++)
                #pragma unroll
                for (int j = 0; j < 4; j++)
                    s4[i][j] += qv[i].x * kv[j].x + qv[i].y * kv[j].y
                              + qv[i].z * kv[j].z + qv[i].w * kv[j].w;
        }

        if (kt == qt) {  // diagonal tile: mask kpos > qpos
            #pragma unroll
            for (int i = 0; i < 4; i++)
                #pragma unroll
                for (int j = 0; j < 4; j++)
                    if (k0 + tx * 4 + j > q0 + ty * 4 + i) s4[i][j] = -1e30f;
        }

        // --- online softmax (rows owned by the 16 threads sharing ty) ---
        #pragma unroll
        for (int i = 0; i < 4; i++) {
            float tm = fmaxf(fmaxf(s4[i][0], s4[i][1]), fmaxf(s4[i][2], s4[i][3]));
            #pragma unroll
            for (int off = 8; off; off >>= 1)
                tm = fmaxf(tm, __shfl_xor_sync(0xffffffffu, tm, off));
            const float nm = fmaxf(m[i], tm);
            const float alpha = __expf(m[i] - nm);
            m[i] = nm;
            float p0 = __expf(s4[i][0] - nm);
            float p1 = __expf(s4[i][1] - nm);
            float p2 = __expf(s4[i][2] - nm);
            float p3 = __expf(s4[i][3] - nm);
            float rs = p0 + p1 + p2 + p3;
            #pragma unroll
            for (int off = 8; off; off >>= 1)
                rs += __shfl_xor_sync(0xffffffffu, rs, off);
            l[i] = l[i] * alpha + rs;
            #pragma unroll
            for (int j = 0; j < 8; j++) o[i][j] *= alpha;
            *(float4*)&Ps[(ty * 4 + i) * 64 + tx * 4] = make_float4(p0, p1, p2, p3);
        }
        __syncthreads();

        // --- O += P @ V : thread covers out cols tx*8..tx*8+7 ---
        const float* vp = &Vs[tx * 8];
        #pragma unroll 4
        for (int k4 = 0; k4 < 64; k4 += 4) {
            float4 pr[4];
            #pragma unroll
            for (int i = 0; i < 4; i++)
                pr[i] = *(const float4*)&Ps[(ty * 4 + i) * 64 + k4];
            #pragma unroll
            for (int kk = 0; kk < 4; kk++) {
                float4 v0 = *(const float4*)(vp + (size_t)(k4 + kk) * 128);
                float4 v1 = *(const float4*)(vp + (size_t)(k4 + kk) * 128 + 4);
                #pragma unroll
                for (int i = 0; i < 4; i++) {
                    float p = (kk == 0) ? pr[i].x : (kk == 1) ? pr[i].y
                            : (kk == 2) ? pr[i].z : pr[i].w;
                    o[i][0] += p * v0.x; o[i][1] += p * v0.y;
                    o[i][2] += p * v0.z; o[i][3] += p * v0.w;
                    o[i][4] += p * v1.x; o[i][5] += p * v1.y;
                    o[i][6] += p * v1.z; o[i][7] += p * v1.w;
                }
            }
        }
    }

    // write O / l  → attn buffer laid out [row][h*128+d]
    #pragma unroll
    for (int i = 0; i < 4; i++) {
        const float inv = 1.0f / l[i];
        float* op = out + ((size_t)(b * S_LEN + q0 + ty * 4 + i)) * H_DIM + h * HD + tx * 8;
        *(float4*)op       = make_float4(o[i][0]*inv, o[i][1]*inv, o[i][2]*inv, o[i][3]*inv);
        *(float4*)(op + 4) = make_float4(o[i][4]*inv, o[i][5]*inv, o[i][6]*inv, o[i][7]*inv);
    }
}

// ---------------------------------------------------------------------------
// SiLU(gate) * up, float4 elementwise
// ---------------------------------------------------------------------------
__global__ __launch_bounds__(256) void silu_mul_k(
    const float4* __restrict__ g, const float4* __restrict__ u,
    float4* __restrict__ y, int n4)
{
    int i = blockIdx.x * 256 + threadIdx.x;
    if (i >= n4) return;
    float4 a = g[i], b = u[i], r;
    r.x = a.x / (1.0f + __expf(-a.x)) * b.x;
    r.y = a.y / (1.0f + __expf(-a.y)) * b.y;
    r.z = a.z / (1.0f + __expf(-a.z)) * b.z;
    r.w = a.w / (1.0f + __expf(-a.w)) * b.w;
    y[i] = r;
}

// ---------------------------------------------------------------------------
// Launch
// ---------------------------------------------------------------------------
extern "C" void kernel_launch(void* const* d_in, const int* in_sizes, int n_in,
                              void* d_out, int out_size)
{
    const float* hidden = (const float*)d_in[0];
    // d_in[1] = attention_mask (pure causal — implemented directly)
    const float* q_w    = (const float*)d_in[2];
    const float* k_w    = (const float*)d_in[3];
    const float* v_w    = (const float*)d_in[4];
    const float* o_w    = (const float*)d_in[5];
    const float* gate_w = (const float*)d_in[6];
    const float* up_w   = (const float*)d_in[7];
    const float* down_w = (const float*)d_in[8];
    const float* ln1    = (const float*)d_in[9];
    const float* ln2    = (const float*)d_in[10];
    float* out = (float*)d_out;

    float *xn, *qkv, *attn, *hbuf, *gate, *up, *ff;
    cudaGetSymbolAddress((void**)&xn,   g_xn);
    cudaGetSymbolAddress((void**)&qkv,  g_qkv);
    cudaGetSymbolAddress((void**)&attn, g_attn);
    cudaGetSymbolAddress((void**)&hbuf, g_h);
    cudaGetSymbolAddress((void**)&gate, g_gate);
    cudaGetSymbolAddress((void**)&up,   g_up);
    cudaGetSymbolAddress((void**)&ff,   g_ff);

    cudaFuncSetAttribute(flash_k, cudaFuncAttributeMaxDynamicSharedMemorySize, FLASH_SMEM);

    // 1) rmsnorm(hidden) -> xn
    rmsnorm_k<<<MROWS, 256>>>(hidden, ln1, xn);

    // 2) QKV projections into fused buffer [row][4096]
    gemm_nt<<<dim3(16, 32), 256>>>(xn, H_DIM, q_w, H_DIM, nullptr, qkv,        QKV_LD, H_DIM);
    gemm_nt<<<dim3( 8, 32), 256>>>(xn, H_DIM, k_w, H_DIM, nullptr, qkv + 2048, QKV_LD, H_DIM);
    gemm_nt<<<dim3( 8, 32), 256>>>(xn, H_DIM, v_w, H_DIM, nullptr, qkv + 3072, QKV_LD, H_DIM);

    // 3) causal flash attention -> attn [row][nh*hd]
    flash_k<<<dim3(S_LEN / 64, NHEADS, B_SZ), 256, FLASH_SMEM>>>(qkv, attn);

    // 4) O projection + residual -> hbuf
    gemm_nt<<<dim3(16, 32), 256>>>(attn, H_DIM, o_w, H_DIM, hidden, hbuf, H_DIM, H_DIM);

    // 5) rmsnorm(hbuf) -> xn
    rmsnorm_k<<<MROWS, 256>>>(hbuf, ln2, xn);

    // 6) gate/up projections
    gemm_nt<<<dim3(44, 32), 256>>>(xn, H_DIM, gate_w, H_DIM, nullptr, gate, FF_DIM, H_DIM);
    gemm_nt<<<dim3(44, 32), 256>>>(xn, H_DIM, up_w,   H_DIM, nullptr, up,   FF_DIM, H_DIM);

    // 7) silu(gate) * up -> ff
    {
        int n4 = MROWS * FF_DIM / 4;
        silu_mul_k<<<(n4 + 255) / 256, 256>>>((const float4*)gate, (const float4*)up,
                                              (float4*)ff, n4);
    }

    // 8) down projection + residual -> out
    gemm_nt<<<dim3(16, 32), 256>>>(ff, FF_DIM, down_w, FF_DIM, hbuf, out, H_DIM, FF_DIM);
}

// round 4
// speedup vs baseline: 1.0013x; 1.0013x over previous
#include <cuda_runtime.h>
#include <cstdint>
#include <cstddef>

// Problem constants
#define H_DIM   2048
#define S_LEN   2048
#define B_SZ    2
#define NHEADS  16
#define NKVH    8
#define HD      128
#define FF_DIM  5632
#define MROWS   (B_SZ * S_LEN)          // 4096
#define QKV_LD  4096                    // q(2048) | k(1024) | v(1024)
#define ATT_SCALE 0.08838834764831845f  // 1/sqrt(128)

// ---------------------------------------------------------------------------
// Scratch (allocation is forbidden; __device__ globals are the sanctioned path)
// ---------------------------------------------------------------------------
__device__ float g_xn  [(size_t)MROWS * H_DIM];   // rmsnorm output (reused twice)
__device__ float g_qkv [(size_t)MROWS * QKV_LD];
__device__ float g_attn[(size_t)MROWS * H_DIM];
__device__ float g_h   [(size_t)MROWS * H_DIM];   // residual-1 output
__device__ float g_gate[(size_t)MROWS * FF_DIM];
__device__ float g_up  [(size_t)MROWS * FF_DIM];
__device__ float g_ff  [(size_t)MROWS * FF_DIM];

// ---------------------------------------------------------------------------
// RMSNorm: one block per row (H=2048), 256 threads, float4
// ---------------------------------------------------------------------------
__global__ __launch_bounds__(256) void rmsnorm_k(
    const float* __restrict__ x, const float* __restrict__ w, float* __restrict__ y)
{
    const int row = blockIdx.x;
    const float4* xr = (const float4*)(x + (size_t)row * H_DIM);
    float4*       yr = (float4*)(y + (size_t)row * H_DIM);
    const float4* w4 = (const float4*)w;
    const int tid = threadIdx.x;

    float4 v0 = xr[tid];
    float4 v1 = xr[tid + 256];
    float s = v0.x*v0.x + v0.y*v0.y + v0.z*v0.z + v0.w*v0.w
            + v1.x*v1.x + v1.y*v1.y + v1.z*v1.z + v1.w*v1.w;

    #pragma unroll
    for (int off = 16; off; off >>= 1) s += __shfl_xor_sync(0xffffffffu, s, off);

    __shared__ float red[8];
    if ((tid & 31) == 0) red[tid >> 5] = s;
    __syncthreads();
    float tot = red[0] + red[1] + red[2] + red[3] + red[4] + red[5] + red[6] + red[7];
    const float inv = rsqrtf(tot * (1.0f / H_DIM) + 1e-6f);

    float4 w0 = w4[tid], w1 = w4[tid + 256];
    float4 o0, o1;
    o0.x = v0.x * inv * w0.x; o0.y = v0.y * inv * w0.y;
    o0.z = v0.z * inv * w0.z; o0.w = v0.w * inv * w0.w;
    o1.x = v1.x * inv * w1.x; o1.y = v1.y * inv * w1.y;
    o1.z = v1.z * inv * w1.z; o1.w = v1.w * inv * w1.w;
    yr[tid] = o0;
    yr[tid + 256] = o1;
}

// ---------------------------------------------------------------------------
// NT GEMM: C[m,n] = sum_k A[m,k] * B[n,k]  (+ optional residual, res ld == ldc)
// BM=BN=128, BK=16, 256 threads, 8x8 per thread.
// Grid: (N/128, M/128). All shapes here are multiples of 128 / K mult of 16.
// ---------------------------------------------------------------------------
__global__ __launch_bounds__(256) void gemm_nt(
    const float* __restrict__ A, int lda,
    const float* __restrict__ B, int ldb,
    const float* __restrict__ Res,
    float* __restrict__ C, int ldc, int K)
{
    __shared__ __align__(16) float As[16][132];
    __shared__ __align__(16) float Bs[16][132];

    const int tid = threadIdx.x;
    const int tx = tid & 15, ty = tid >> 4;
    const int m0 = blockIdx.y * 128;
    const int n0 = blockIdx.x * 128;

    const float* Ag = A + (size_t)m0 * lda;
    const float* Bg = B + (size_t)n0 * ldb;

    float acc[8][8];
    #pragma unroll
    for (int i = 0; i < 8; i++)
        #pragma unroll
        for (int j = 0; j < 8; j++) acc[i][j] = 0.0f;

    const int r0 = tid >> 2;         // 0..63
    const int c4 = (tid & 3) << 2;   // 0,4,8,12

    for (int k0 = 0; k0 < K; k0 += 16) {
        float4 a0 = *(const float4*)(Ag + (size_t)r0        * lda + k0 + c4);
        float4 a1 = *(const float4*)(Ag + (size_t)(r0 + 64) * lda + k0 + c4);
        float4 b0 = *(const float4*)(Bg + (size_t)r0        * ldb + k0 + c4);
        float4 b1 = *(const float4*)(Bg + (size_t)(r0 + 64) * ldb + k0 + c4);

        As[c4+0][r0] = a0.x; As[c4+1][r0] = a0.y; As[c4+2][r0] = a0.z; As[c4+3][r0] = a0.w;
        As[c4+0][r0+64] = a1.x; As[c4+1][r0+64] = a1.y; As[c4+2][r0+64] = a1.z; As[c4+3][r0+64] = a1.w;
        Bs[c4+0][r0] = b0.x; Bs[c4+1][r0] = b0.y; Bs[c4+2][r0] = b0.z; Bs[c4+3][r0] = b0.w;
        Bs[c4+0][r0+64] = b1.x; Bs[c4+1][r0+64] = b1.y; Bs[c4+2][r0+64] = b1.z; Bs[c4+3][r0+64] = b1.w;
        __syncthreads();

        #pragma unroll
        for (int kk = 0; kk < 16; kk++) {
            float a[8], b[8];
            *(float4*)(a)     = *(const float4*)&As[kk][ty * 8];
            *(float4*)(a + 4) = *(const float4*)&As[kk][ty * 8 + 4];
            *(float4*)(b)     = *(const float4*)&Bs[kk][tx * 8];
            *(float4*)(b + 4) = *(const float4*)&Bs[kk][tx * 8 + 4];
            #pragma unroll
            for (int i = 0; i < 8; i++)
                #pragma unroll
                for (int j = 0; j < 8; j++)
                    acc[i][j] += a[i] * b[j];
        }
        __syncthreads();
    }

    #pragma unroll
    for (int i = 0; i < 8; i++) {
        const size_t m = (size_t)(m0 + ty * 8 + i);
        float* cp = C + m * ldc + n0 + tx * 8;
        float4 v0 = make_float4(acc[i][0], acc[i][1], acc[i][2], acc[i][3]);
        float4 v1 = make_float4(acc[i][4], acc[i][5], acc[i][6], acc[i][7]);
        if (Res) {
            const float* rp = Res + m * ldc + n0 + tx * 8;
            float4 e0 = *(const float4*)rp;
            float4 e1 = *(const float4*)(rp + 4);
            v0.x += e0.x; v0.y += e0.y; v0.z += e0.z; v0.w += e0.w;
            v1.x += e1.x; v1.y += e1.y; v1.z += e1.z; v1.w += e1.w;
        }
        *(float4*)cp = v0;
        *(float4*)(cp + 4) = v1;
    }
}

// ---------------------------------------------------------------------------
// Causal flash attention, fp32, GQA (kv head = h >> 1).
// Grid (32, 16, 2): q-tile 64, k-tile 64. Block 256 (16x16 logical).
// Each thread: 4 q-rows (ty*4+i) x [4 score cols (tx*4+j) | 8 out cols (tx*8+j)].
// Smem: Qs[64][128] + Ks[64][132] + Vs[64][128] + Ps[64][64] = 113 KB dynamic.
// ---------------------------------------------------------------------------
#define FLASH_SMEM ((64*128 + 64*132 + 64*128 + 64*64) * 4)

__global__ __launch_bounds__(256) void flash_k(
    const float* __restrict__ qkv, float* __restrict__ out)
{
    extern __shared__ float sm[];
    float* Qs = sm;                 // [64][128]
    float* Ks = Qs + 64 * 128;      // [64][132] (padded vs bank conflicts)
    float* Vs = Ks + 64 * 132;      // [64][128]
    float* Ps = Vs + 64 * 128;      // [64][64]

    const int qt = gridDim.x - 1 - blockIdx.x;   // high q-tiles first (causal balance)
    const int h  = blockIdx.y;
    const int b  = blockIdx.z;
    const int kvh = h >> 1;                      // GROUPS = 2
    const int q0 = qt * 64;
    const int tid = threadIdx.x;
    const int tx = tid & 15, ty = tid >> 4;

    const float* qbase = qkv + ((size_t)(b * S_LEN + q0)) * QKV_LD + h * HD;
    const float* kbase = qkv + ((size_t)(b * S_LEN)) * QKV_LD + 2048 + kvh * HD;
    const float* vbase = kbase + 1024;

    // Load Q tile (pre-scaled by 1/sqrt(HD))
    #pragma unroll
    for (int t = 0; t < 8; t++) {
        int idx = tid + t * 256;
        int r = idx >> 5;
        int d4 = (idx & 31) << 2;
        float4 v = *(const float4*)(qbase + (size_t)r * QKV_LD + d4);
        v.x *= ATT_SCALE; v.y *= ATT_SCALE; v.z *= ATT_SCALE; v.w *= ATT_SCALE;
        *(float4*)&Qs[r * 128 + d4] = v;
    }

    float m[4], l[4], o[4][8];
    #pragma unroll
    for (int i = 0; i < 4; i++) {
        m[i] = -1e30f; l[i] = 0.0f;
        #pragma unroll
        for (int j = 0; j < 8; j++) o[i][j] = 0.0f;
    }

    for (int kt = 0; kt <= qt; kt++) {
        const int k0 = kt * 64;
        __syncthreads();  // protect Ks/Vs/Ps reuse
        #pragma unroll
        for (int t = 0; t < 8; t++) {
            int idx = tid + t * 256;
            int r = idx >> 5;
            int d4 = (idx & 31) << 2;
            *(float4*)&Ks[r * 132 + d4] = *(const float4*)(kbase + (size_t)(k0 + r) * QKV_LD + d4);
            *(float4*)&Vs[r * 128 + d4] = *(const float4*)(vbase + (size_t)(k0 + r) * QKV_LD + d4);
        }
        __syncthreads();

        // --- scores: s[i][j] = q_row(ty*4+i) . k_row(tx*4+j) ---
        float s4[4][4];
        #pragma unroll
        for (int i = 0; i < 4; i++)
            #pragma unroll
            for (int j = 0; j < 4; j++) s4[i][j] = 0.0f;

        const float* qp = &Qs[(ty * 4) * 128];
        const float* kp = &Ks[(tx * 4) * 132];
        #pragma unroll 8
        for (int d = 0; d < 128; d += 4) {
            float4 qv[4], kv[4];
            #pragma unroll
            for (int i = 0; i < 4; i++) qv[i] = *(const float4*)(qp + i * 128 + d);
            #pragma unroll
            for (int j = 0; j < 4; j++) kv[j] = *(const float4*)(kp + j * 132 + d);
            #pragma unroll
            for (int i = 0; i < 4; i++)
                #pragma unroll
                for (int j = 0; j < 4; j++)
                    s4[i][j] += qv[i].x * kv[j].x + qv[i].y * kv[j].y
                              + qv[i].z * kv[j].z + qv[i].w * kv[j].w;
        }

        if (kt == qt) {  // diagonal tile: mask kpos > qpos
            #pragma unroll
            for (int i = 0; i < 4; i++)
                #pragma unroll
                for (int j = 0; j < 4; j++)
                    if (k0 + tx * 4 + j > q0 + ty * 4 + i) s4[i][j] = -1e30f;
        }

        // --- online softmax (rows owned by the 16 threads sharing ty) ---
        #pragma unroll
        for (int i = 0; i < 4; i++) {
            float tm = fmaxf(fmaxf(s4[i][0], s4[i][1]), fmaxf(s4[i][2], s4[i][3]));
            #pragma unroll
            for (int off = 8; off; off >>= 1)
                tm = fmaxf(tm, __shfl_xor_sync(0xffffffffu, tm, off));
            const float nm = fmaxf(m[i], tm);
            const float alpha = __expf(m[i] - nm);
            m[i] = nm;
            float p0 = __expf(s4[i][0] - nm);
            float p1 = __expf(s4[i][1] - nm);
            float p2 = __expf(s4[i][2] - nm);
            float p3 = __expf(s4[i][3] - nm);
            float rs = p0 + p1 + p2 + p3;
            #pragma unroll
            for (int off = 8; off; off >>= 1)
                rs += __shfl_xor_sync(0xffffffffu, rs, off);
            l[i] = l[i] * alpha + rs;
            #pragma unroll
            for (int j = 0; j < 8; j++) o[i][j] *= alpha;
            *(float4*)&Ps[(ty * 4 + i) * 64 + tx * 4] = make_float4(p0, p1, p2, p3);
        }
        __syncthreads();

        // --- O += P @ V : thread covers out cols tx*8..tx*8+7 ---
        const float* vp = &Vs[tx * 8];
        #pragma unroll 4
        for (int k4 = 0; k4 < 64; k4 += 4) {
            float4 pr[4];
            #pragma unroll
            for (int i = 0; i < 4; i++)
                pr[i] = *(const float4*)&Ps[(ty * 4 + i) * 64 + k4];
            #pragma unroll
            for (int kk = 0; kk < 4; kk++) {
                float4 v0 = *(const float4*)(vp + (size_t)(k4 + kk) * 128);
                float4 v1 = *(const float4*)(vp + (size_t)(k4 + kk) * 128 + 4);
                #pragma unroll
                for (int i = 0; i < 4; i++) {
                    float p = (kk == 0) ? pr[i].x : (kk == 1) ? pr[i].y
                            : (kk == 2) ? pr[i].z : pr[i].w;
                    o[i][0] += p * v0.x; o[i][1] += p * v0.y;
                    o[i][2] += p * v0.z; o[i][3] += p * v0.w;
                    o[i][4] += p * v1.x; o[i][5] += p * v1.y;
                    o[i][6] += p * v1.z; o[i][7] += p * v1.w;
                }
            }
        }
    }

    // write O / l  → attn buffer laid out [row][h*128+d]
    #pragma unroll
    for (int i = 0; i < 4; i++) {
        const float inv = 1.0f / l[i];
        float* op = out + ((size_t)(b * S_LEN + q0 + ty * 4 + i)) * H_DIM + h * HD + tx * 8;
        *(float4*)op       = make_float4(o[i][0]*inv, o[i][1]*inv, o[i][2]*inv, o[i][3]*inv);
        *(float4*)(op + 4) = make_float4(o[i][4]*inv, o[i][5]*inv, o[i][6]*inv, o[i][7]*inv);
    }
}

// ---------------------------------------------------------------------------
// SiLU(gate) * up, float4 elementwise
// ---------------------------------------------------------------------------
__global__ __launch_bounds__(256) void silu_mul_k(
    const float4* __restrict__ g, const float4* __restrict__ u,
    float4* __restrict__ y, int n4)
{
    int i = blockIdx.x * 256 + threadIdx.x;
    if (i >= n4) return;
    float4 a = g[i], b = u[i], r;
    r.x = a.x / (1.0f + __expf(-a.x)) * b.x;
    r.y = a.y / (1.0f + __expf(-a.y)) * b.y;
    r.z = a.z / (1.0f + __expf(-a.z)) * b.z;
    r.w = a.w / (1.0f + __expf(-a.w)) * b.w;
    y[i] = r;
}

// ---------------------------------------------------------------------------
// Launch
// ---------------------------------------------------------------------------
extern "C" void kernel_launch(void* const* d_in, const int* in_sizes, int n_in,
                              void* d_out, int out_size)
{
    const float* hidden = (const float*)d_in[0];
    // d_in[1] = attention_mask (pure causal — implemented directly)
    const float* q_w    = (const float*)d_in[2];
    const float* k_w    = (const float*)d_in[3];
    const float* v_w    = (const float*)d_in[4];
    const float* o_w    = (const float*)d_in[5];
    const float* gate_w = (const float*)d_in[6];
    const float* up_w   = (const float*)d_in[7];
    const float* down_w = (const float*)d_in[8];
    const float* ln1    = (const float*)d_in[9];
    const float* ln2    = (const float*)d_in[10];
    float* out = (float*)d_out;

    float *xn, *qkv, *attn, *hbuf, *gate, *up, *ff;
    cudaGetSymbolAddress((void**)&xn,   g_xn);
    cudaGetSymbolAddress((void**)&qkv,  g_qkv);
    cudaGetSymbolAddress((void**)&attn, g_attn);
    cudaGetSymbolAddress((void**)&hbuf, g_h);
    cudaGetSymbolAddress((void**)&gate, g_gate);
    cudaGetSymbolAddress((void**)&up,   g_up);
    cudaGetSymbolAddress((void**)&ff,   g_ff);

    cudaFuncSetAttribute(flash_k, cudaFuncAttributeMaxDynamicSharedMemorySize, FLASH_SMEM);

    // 1) rmsnorm(hidden) -> xn
    rmsnorm_k<<<MROWS, 256>>>(hidden, ln1, xn);

    // 2) QKV projections into fused buffer [row][4096]
    gemm_nt<<<dim3(16, 32), 256>>>(xn, H_DIM, q_w, H_DIM, nullptr, qkv,        QKV_LD, H_DIM);
    gemm_nt<<<dim3( 8, 32), 256>>>(xn, H_DIM, k_w, H_DIM, nullptr, qkv + 2048, QKV_LD, H_DIM);
    gemm_nt<<<dim3( 8, 32), 256>>>(xn, H_DIM, v_w, H_DIM, nullptr, qkv + 3072, QKV_LD, H_DIM);

    // 3) causal flash attention -> attn [row][nh*hd]
    flash_k<<<dim3(S_LEN / 64, NHEADS, B_SZ), 256, FLASH_SMEM>>>(qkv, attn);

    // 4) O projection + residual -> hbuf
    gemm_nt<<<dim3(16, 32), 256>>>(attn, H_DIM, o_w, H_DIM, hidden, hbuf, H_DIM, H_DIM);

    // 5) rmsnorm(hbuf) -> xn
    rmsnorm_k<<<MROWS, 256>>>(hbuf, ln2, xn);

    // 6) gate/up projections
    gemm_nt<<<dim3(44, 32), 256>>>(xn, H_DIM, gate_w, H_DIM, nullptr, gate, FF_DIM, H_DIM);
    gemm_nt<<<dim3(44, 32), 256>>>(xn, H_DIM, up_w,   H_DIM, nullptr, up,   FF_DIM, H_DIM);

    // 7) silu(gate) * up -> ff
    {
        int n4 = MROWS * FF_DIM / 4;
        silu_mul_k<<<(n4 + 255) / 256, 256>>>((const float4*)gate, (const float4*)up,
                                              (float4*)ff, n4);
    }

    // 8) down projection + residual -> out
    gemm_nt<<<dim3(16, 32), 256>>>(ff, FF_DIM, down_w, FF_DIM, hbuf, out, H_DIM, FF_DIM);
}